// round 9
// baseline (speedup 1.0000x reference)
#include <cuda_runtime.h>
#include <cuda_fp16.h>
#include <cuda_bf16.h>
#include <cstdint>

// Problem constants
#define C_DIM   192
#define HEADS   8
#define HD      24          // head dim = 192/8
#define HH      64
#define WW      64
#define NPIX    4096        // 64*64
#define QKV_CH  576         // 3*C

// ---------------- scratch (static device globals; no allocs) ----------------
__device__ float g_xln[C_DIM * NPIX];                 // 3 MB
__device__ float g_qkv[QKV_CH * NPIX];                // 9 MB
__device__ float g_q32[C_DIM * NPIX];                 // 3 MB (dwconv Q out, fp32)
__device__ float g_att[C_DIM * NPIX];                 // 3 MB
// prepacked K (hi/lo fp16, [head][key][32] with cols 24..31 zero) and V fp16
__device__ unsigned short g_kh16[HEADS * NPIX * 32];  // 2 MB
__device__ unsigned short g_kl16[HEADS * NPIX * 32];  // 2 MB
__device__ unsigned short g_vh16[C_DIM * NPIX];       // 1.5 MB

// ---------------- small helpers ----------------
__device__ __forceinline__ float ex2f_fast(float x) {
    float r;
    asm("ex2.approx.f32 %0, %1;" : "=f"(r) : "f"(x));
    return r;
}

// ---------------- Kernel 1: per-pixel LayerNorm over channels ----------------
__global__ void ln_kernel(const float* __restrict__ x,
                          const float* __restrict__ gamma,
                          const float* __restrict__ beta,
                          float* __restrict__ xln) {
    int p = blockIdx.x * blockDim.x + threadIdx.x;
    if (p >= NPIX) return;
    float s = 0.f, s2 = 0.f;
    #pragma unroll 8
    for (int c = 0; c < C_DIM; c++) {
        float v = x[c * NPIX + p];
        s += v;
        s2 = fmaf(v, v, s2);
    }
    const float invC = 1.0f / (float)C_DIM;
    float mean = s * invC;
    float var = s2 * invC - mean * mean;
    float inv = rsqrtf(var + 1e-5f);
    #pragma unroll 8
    for (int c = 0; c < C_DIM; c++) {
        float v = (x[c * NPIX + p] - mean) * inv;
        xln[c * NPIX + p] = fmaf(v, gamma[c], beta[c]);
    }
}

// ---------------- Kernel 2: GEMM  Y[O,N] = W[O,C] @ X[C,N] (+ optional residual) ----
__global__ __launch_bounds__(256) void gemm_kernel(
        const float* __restrict__ W, const float* __restrict__ X,
        const float* __restrict__ resid, float* __restrict__ Y,
        int O, int C, int N) {
    __shared__ __align__(16) float As[16][68];   // [k][o], padded
    __shared__ __align__(16) float Bs[16][64];   // [k][n]
    int tid = threadIdx.x;
    int tx = tid & 15;       // N dir
    int ty = tid >> 4;       // O dir
    int o0 = blockIdx.y * 64;
    int n0 = blockIdx.x * 64;

    float acc[4][4];
    #pragma unroll
    for (int i = 0; i < 4; i++)
        #pragma unroll
        for (int j = 0; j < 4; j++) acc[i][j] = 0.f;

    for (int k0 = 0; k0 < C; k0 += 16) {
        {
            int row = tid >> 2;
            int col = (tid & 3) * 4;
            float4 a = *(const float4*)&W[(o0 + row) * C + k0 + col];
            As[col + 0][row] = a.x;
            As[col + 1][row] = a.y;
            As[col + 2][row] = a.z;
            As[col + 3][row] = a.w;
        }
        {
            int row = tid >> 4;
            int col = (tid & 15) * 4;
            *(float4*)&Bs[row][col] = *(const float4*)&X[(k0 + row) * N + n0 + col];
        }
        __syncthreads();
        #pragma unroll
        for (int k = 0; k < 16; k++) {
            float4 a4 = *(const float4*)&As[k][ty * 4];
            float4 b4 = *(const float4*)&Bs[k][tx * 4];
            float a[4] = {a4.x, a4.y, a4.z, a4.w};
            float b[4] = {b4.x, b4.y, b4.z, b4.w};
            #pragma unroll
            for (int i = 0; i < 4; i++)
                #pragma unroll
                for (int j = 0; j < 4; j++)
                    acc[i][j] = fmaf(a[i], b[j], acc[i][j]);
        }
        __syncthreads();
    }

    #pragma unroll
    for (int i = 0; i < 4; i++) {
        int o = o0 + ty * 4 + i;
        int n = n0 + tx * 4;
        float4 r = make_float4(acc[i][0], acc[i][1], acc[i][2], acc[i][3]);
        if (resid) {
            float4 rv = *(const float4*)&resid[o * N + n];
            r.x += rv.x; r.y += rv.y; r.z += rv.z; r.w += rv.w;
        }
        *(float4*)&Y[o * N + n] = r;
    }
}

// ---------------- Kernel 3: depthwise 3x3 conv + bias, fused K/V prepack ----
// Q channels -> fp32 qout; K channels -> hi/lo fp16 transposed [h][key][32];
// V channels -> fp16 [c][key].
__global__ void dwconv_kernel(const float* __restrict__ in,
                              const float* __restrict__ w,
                              const float* __restrict__ b,
                              float* __restrict__ qout,
                              unsigned short* __restrict__ kh,
                              unsigned short* __restrict__ kl,
                              unsigned short* __restrict__ vh) {
    int idx = blockIdx.x * blockDim.x + threadIdx.x;
    if (idx >= QKV_CH * NPIX) return;
    int p = idx & (NPIX - 1);
    int xx = idx & (WW - 1);
    int yy = (idx >> 6) & (HH - 1);
    int ch = idx >> 12;
    const float* wp = &w[ch * 9];
    const float* base = &in[ch * NPIX];
    float acc = b[ch];
    #pragma unroll
    for (int dy = -1; dy <= 1; dy++) {
        int y2 = yy + dy;
        if (y2 < 0 || y2 >= HH) continue;
        #pragma unroll
        for (int dx = -1; dx <= 1; dx++) {
            int x2 = xx + dx;
            if (x2 < 0 || x2 >= WW) continue;
            acc = fmaf(base[y2 * WW + x2], wp[(dy + 1) * 3 + (dx + 1)], acc);
        }
    }
    if (ch < C_DIM) {
        qout[idx] = acc;
    } else if (ch < 2 * C_DIM) {
        int cc = ch - C_DIM;
        int hh2 = cc / HD;
        int dd = cc % HD;
        __half hi = __float2half_rn(acc);
        float lo = acc - __half2float(hi);
        size_t o = ((size_t)(hh2 * NPIX + p)) * 32 + dd;
        kh[o] = __half_as_ushort(hi);
        kl[o] = __half_as_ushort(__float2half_rn(lo));
    } else {
        vh[(size_t)(ch - 2 * C_DIM) * NPIX + p] =
            __half_as_ushort(__float2half_rn(acc));
    }
}

// ---------------- Kernel 4: tensor-core flash attention ----------------
// 256 threads = 8 warps, 128 queries (16/warp), full 4096 keys in 64-key
// chunks. K/V arrive prepacked fp16 via cp.async (3-stage pipeline, 1 barrier
// per chunk). QK^T compensated hi/lo fp16 (err ~2^-21), PV fp16 (err ~1e-4).
#define ATT_Q  128
#define ATT_K  64
#define NCHUNK (NPIX / ATT_K)

// smem layout in halves (dynamic). Q rows padded to 40, K rows 40, V rows 72.
#define OQH 0                         // Qh [128][40]
#define OQL 5120                      // Ql [128][40]
#define OKB 10240                     // K bufs: 3 x (hi 64*40 + lo 64*40)
#define OVB 25600                     // V bufs: 3 x 24*72
#define SM_HALVES 30784
#define SMEM_BYTES (SM_HALVES * 2)    // 61568

__device__ __forceinline__ void mma16816(float c[4], const uint32_t a[4],
                                         uint32_t b0, uint32_t b1) {
    asm volatile(
        "mma.sync.aligned.m16n8k16.row.col.f32.f16.f16.f32 "
        "{%0,%1,%2,%3}, {%4,%5,%6,%7}, {%8,%9}, {%0,%1,%2,%3};"
        : "+f"(c[0]), "+f"(c[1]), "+f"(c[2]), "+f"(c[3])
        : "r"(a[0]), "r"(a[1]), "r"(a[2]), "r"(a[3]), "r"(b0), "r"(b1));
}

__device__ __forceinline__ void ldsm_x4(uint32_t& r0, uint32_t& r1,
                                        uint32_t& r2, uint32_t& r3, uint32_t addr) {
    asm volatile("ldmatrix.sync.aligned.m8n8.x4.shared.b16 {%0,%1,%2,%3}, [%4];"
                 : "=r"(r0), "=r"(r1), "=r"(r2), "=r"(r3) : "r"(addr));
}

__device__ __forceinline__ void cp16(uint32_t dst, const void* src) {
    asm volatile("cp.async.cg.shared.global [%0], [%1], 16;"
                 :: "r"(dst), "l"(src));
}

__device__ __forceinline__ uint32_t packh2(float x, float y) {
    __half2 h = __floats2half2_rn(x, y);   // low <- x, high <- y
    return *(uint32_t*)&h;
}

__global__ __launch_bounds__(256, 2) void attn_mma_kernel(
        const float* __restrict__ q32,
        const unsigned short* __restrict__ kh,
        const unsigned short* __restrict__ kl,
        const unsigned short* __restrict__ vh,
        const float* __restrict__ temp,
        float* __restrict__ att) {
    extern __shared__ __align__(16) __half sm[];
    const int tid = threadIdx.x;
    const int lane = tid & 31;
    const int warp = tid >> 5;
    const int g = lane >> 2;      // row group 0..7
    const int t = lane & 3;       // thread-in-group

    const int h = blockIdx.y;
    const int q0 = blockIdx.x * ATT_Q;
    const float scale = temp[h] * 1.4426950408889634f;  // temperature * log2(e)

    const float* qg = q32 + (h * HD) * NPIX;
    const unsigned short* khg = kh + (size_t)h * NPIX * 32;
    const unsigned short* klg = kl + (size_t)h * NPIX * 32;
    const unsigned short* vg  = vh + (size_t)(h * HD) * NPIX;

    const uint32_t smb = (uint32_t)__cvta_generic_to_shared(sm);

    // ---- zero Q region (incl. pads) and K pad columns (24..31, all bufs) ----
    {
        uint32_t* smw = (uint32_t*)sm;
        for (int i = tid; i < 5120; i += 256) smw[i] = 0;          // Q hi/lo
        for (int i = tid; i < 1536; i += 256) {                    // K pads
            int wds = i & 3;               // word within 8-half pad
            int r2 = i >> 2;               // 0..383 rows (3 bufs x 2 parts x 64)
            int buf = r2 >> 7;
            int rem = r2 & 127;
            int part = rem >> 6;
            int row = rem & 63;
            int halfoff = OKB + buf * 5120 + part * 2560 + row * 40 + 24;
            smw[(halfoff >> 1) + wds] = 0;
        }
    }
    __syncthreads();

    // ---- issue cp.async for chunks 0 and 1 ----
    auto issue_chunk = [&](int b, int m0) {
        uint32_t kdstH = smb + (OKB + b * 5120) * 2;
        uint32_t kdstL = kdstH + 2560 * 2;
        uint32_t vdst  = smb + (OVB + b * 1728) * 2;
        #pragma unroll
        for (int i = tid; i < 576; i += 256) {
            if (i < 384) {
                int r = i;
                int part = r >= 192;
                r -= part * 192;
                int key = r / 3;
                int c = r - key * 3;
                const unsigned short* src =
                    (part ? klg : khg) + (size_t)(m0 + key) * 32 + c * 8;
                uint32_t dst = (part ? kdstL : kdstH) + (key * 40 + c * 8) * 2;
                cp16(dst, src);
            } else {
                int r = i - 384;
                int d = r >> 3;
                int c2 = r & 7;
                const unsigned short* src = vg + (size_t)d * NPIX + m0 + c2 * 8;
                uint32_t dst = vdst + (d * 72 + c2 * 8) * 2;
                cp16(dst, src);
            }
        }
        asm volatile("cp.async.commit_group;" ::: "memory");
    };
    issue_chunk(0, 0);
    issue_chunk(1, ATT_K);

    // ---- stage Q (scaled, hi/lo split) ----
    #pragma unroll
    for (int i = 0; i < 6; i++) {
        int e = tid + i * 256;            // 128 q * 12 d-pairs = 1536
        int dp = e >> 7;
        int qq = e & 127;
        float v0 = qg[(2 * dp) * NPIX + q0 + qq] * scale;
        float v1 = qg[(2 * dp + 1) * NPIX + q0 + qq] * scale;
        __half h0 = __float2half_rn(v0);
        __half h1 = __float2half_rn(v1);
        __half l0 = __float2half_rn(v0 - __half2float(h0));
        __half l1 = __float2half_rn(v1 - __half2float(h1));
        *(__half2*)&sm[OQH + qq * 40 + 2 * dp] = __halves2half2(h0, h1);
        *(__half2*)&sm[OQL + qq * 40 + 2 * dp] = __halves2half2(l0, l1);
    }
    __syncthreads();

    // ---- load Q A-fragments (2 k-steps over d 0..31; 24..31 zero pad) ----
    uint32_t aqh[2][4], aql[2][4];
    const int qr = warp * 16 + g;
    #pragma unroll
    for (int ks = 0; ks < 2; ks++) {
        int db = ks * 16 + t * 2;
        aqh[ks][0] = *(const uint32_t*)&sm[OQH + qr * 40 + db];
        aqh[ks][1] = *(const uint32_t*)&sm[OQH + (qr + 8) * 40 + db];
        aqh[ks][2] = *(const uint32_t*)&sm[OQH + qr * 40 + db + 8];
        aqh[ks][3] = *(const uint32_t*)&sm[OQH + (qr + 8) * 40 + db + 8];
        aql[ks][0] = *(const uint32_t*)&sm[OQL + qr * 40 + db];
        aql[ks][1] = *(const uint32_t*)&sm[OQL + (qr + 8) * 40 + db];
        aql[ks][2] = *(const uint32_t*)&sm[OQL + qr * 40 + db + 8];
        aql[ks][3] = *(const uint32_t*)&sm[OQL + (qr + 8) * 40 + db + 8];
    }

    // per-lane ldmatrix offsets
    const int l7 = lane & 7;
    const int lc = (lane >> 3) * 8;
    const uint32_t loff_k = (l7 * 40 + lc) * 2;
    const uint32_t loff_v = (l7 * 72 + lc) * 2;

    float out[3][4];
    #pragma unroll
    for (int i = 0; i < 3; i++)
        #pragma unroll
        for (int j = 0; j < 4; j++) out[i][j] = 0.f;
    float m_a = -1e30f, m_b = -1e30f;   // row maxes (log2 units)
    float l_a = 0.f, l_b = 0.f;         // per-thread PARTIAL row sums

    for (int ch = 0; ch < NCHUNK; ch++) {
        if (ch < NCHUNK - 1)
            asm volatile("cp.async.wait_group 1;" ::: "memory");
        else
            asm volatile("cp.async.wait_group 0;" ::: "memory");
        __syncthreads();
        if (ch + 2 < NCHUNK) issue_chunk((ch + 2) % 3, (ch + 2) * ATT_K);

        const int b = ch % 3;
        const uint32_t kaddr_h = smb + (OKB + b * 5120) * 2 + loff_k;
        const uint32_t kaddr_l = kaddr_h + 2560 * 2;
        const uint32_t vaddr   = smb + (OVB + b * 1728) * 2 + loff_v;

        // ---- S = Q K^T (compensated), 8 n-tiles of 8 keys ----
        float s[8][4];
        #pragma unroll
        for (int nt = 0; nt < 8; nt++) {
            uint32_t h0, h1, h2, h3, L0, L1, L2, L3;
            ldsm_x4(h0, h1, h2, h3, kaddr_h + nt * 640);
            ldsm_x4(L0, L1, L2, L3, kaddr_l + nt * 640);
            s[nt][0] = s[nt][1] = s[nt][2] = s[nt][3] = 0.f;
            mma16816(s[nt], aqh[0], h0, h1);
            mma16816(s[nt], aqh[1], h2, h3);
            mma16816(s[nt], aql[0], h0, h1);
            mma16816(s[nt], aql[1], h2, h3);
            mma16816(s[nt], aqh[0], L0, L1);
            mma16816(s[nt], aqh[1], L2, L3);
        }

        // ---- online softmax (log2 domain); l kept as per-thread partial ----
        float ra = -1e30f, rb = -1e30f;
        #pragma unroll
        for (int nt = 0; nt < 8; nt++) {
            ra = fmaxf(ra, fmaxf(s[nt][0], s[nt][1]));
            rb = fmaxf(rb, fmaxf(s[nt][2], s[nt][3]));
        }
        ra = fmaxf(ra, __shfl_xor_sync(0xffffffffu, ra, 1));
        ra = fmaxf(ra, __shfl_xor_sync(0xffffffffu, ra, 2));
        rb = fmaxf(rb, __shfl_xor_sync(0xffffffffu, rb, 1));
        rb = fmaxf(rb, __shfl_xor_sync(0xffffffffu, rb, 2));
        float nma = fmaxf(m_a, ra);
        float nmb = fmaxf(m_b, rb);
        float ala = ex2f_fast(m_a - nma);
        float alb = ex2f_fast(m_b - nmb);
        m_a = nma; m_b = nmb;
        #pragma unroll
        for (int dnt = 0; dnt < 3; dnt++) {
            out[dnt][0] *= ala; out[dnt][1] *= ala;
            out[dnt][2] *= alb; out[dnt][3] *= alb;
        }
        float sa = 0.f, sb = 0.f;
        #pragma unroll
        for (int nt = 0; nt < 8; nt++) {
            s[nt][0] = ex2f_fast(s[nt][0] - m_a);
            s[nt][1] = ex2f_fast(s[nt][1] - m_a);
            s[nt][2] = ex2f_fast(s[nt][2] - m_b);
            s[nt][3] = ex2f_fast(s[nt][3] - m_b);
            sa += s[nt][0] + s[nt][1];
            sb += s[nt][2] + s[nt][3];
        }
        // deferred-l update: l = l*alpha + partial_sum   (one fmaf, NaN-safe)
        l_a = fmaf(l_a, ala, sa);
        l_b = fmaf(l_b, alb, sb);

        // ---- out += P V  (P: C-layout == A-layout trick), V via LDSM ----
        uint32_t pa[4][4];
        #pragma unroll
        for (int kv = 0; kv < 4; kv++) {
            pa[kv][0] = packh2(s[2 * kv][0],     s[2 * kv][1]);
            pa[kv][1] = packh2(s[2 * kv][2],     s[2 * kv][3]);
            pa[kv][2] = packh2(s[2 * kv + 1][0], s[2 * kv + 1][1]);
            pa[kv][3] = packh2(s[2 * kv + 1][2], s[2 * kv + 1][3]);
        }
        #pragma unroll
        for (int dnt = 0; dnt < 3; dnt++) {
            uint32_t v0, v1, v2, v3, v4, v5, v6, v7;
            ldsm_x4(v0, v1, v2, v3, vaddr + dnt * 1152);        // keys 0..31
            ldsm_x4(v4, v5, v6, v7, vaddr + dnt * 1152 + 64);   // keys 32..63
            mma16816(out[dnt], pa[0], v0, v1);
            mma16816(out[dnt], pa[1], v2, v3);
            mma16816(out[dnt], pa[2], v4, v5);
            mma16816(out[dnt], pa[3], v6, v7);
        }
    }

    // ---- epilogue: reduce l across quad, normalize, store ----
    l_a += __shfl_xor_sync(0xffffffffu, l_a, 1);
    l_a += __shfl_xor_sync(0xffffffffu, l_a, 2);
    l_b += __shfl_xor_sync(0xffffffffu, l_b, 1);
    l_b += __shfl_xor_sync(0xffffffffu, l_b, 2);
    float inva = 1.0f / l_a;
    float invb = 1.0f / l_b;
    int qa = q0 + warp * 16 + g;
    int qb = qa + 8;
    #pragma unroll
    for (int dnt = 0; dnt < 3; dnt++) {
        int c0 = h * HD + dnt * 8 + t * 2;
        att[c0 * NPIX + qa]       = out[dnt][0] * inva;
        att[(c0 + 1) * NPIX + qa] = out[dnt][1] * inva;
        att[c0 * NPIX + qb]       = out[dnt][2] * invb;
        att[(c0 + 1) * NPIX + qb] = out[dnt][3] * invb;
    }
}

// ---------------- launch ----------------
extern "C" void kernel_launch(void* const* d_in, const int* in_sizes, int n_in,
                              void* d_out, int out_size) {
    const float* x      = (const float*)d_in[0];   // [192,4096]
    const float* gamma  = (const float*)d_in[1];   // [192]
    const float* beta   = (const float*)d_in[2];   // [192]
    const float* w_qkv  = (const float*)d_in[3];   // [576,192]
    const float* w_dw   = (const float*)d_in[4];   // [576,9]
    const float* b_dw   = (const float*)d_in[5];   // [576]
    const float* w_proj = (const float*)d_in[6];   // [192,192]
    const float* temper = (const float*)d_in[7];   // [8]
    float* out = (float*)d_out;

    float *xln, *qkvb, *q32, *att;
    unsigned short *kh, *kl, *vh;
    cudaGetSymbolAddress((void**)&xln,  g_xln);
    cudaGetSymbolAddress((void**)&qkvb, g_qkv);
    cudaGetSymbolAddress((void**)&q32,  g_q32);
    cudaGetSymbolAddress((void**)&att,  g_att);
    cudaGetSymbolAddress((void**)&kh,   g_kh16);
    cudaGetSymbolAddress((void**)&kl,   g_kl16);
    cudaGetSymbolAddress((void**)&vh,   g_vh16);

    cudaFuncSetAttribute(attn_mma_kernel,
                         cudaFuncAttributeMaxDynamicSharedMemorySize, SMEM_BYTES);

    // 1. LayerNorm
    ln_kernel<<<NPIX / 256, 256>>>(x, gamma, beta, xln);

    // 2. qkv = w_qkv @ xln   [576,4096]
    {
        dim3 grid(NPIX / 64, QKV_CH / 64);
        gemm_kernel<<<grid, 256>>>(w_qkv, xln, nullptr, qkvb, QKV_CH, C_DIM, NPIX);
    }

    // 3. depthwise 3x3 + bias, fused K/V fp16 prepack
    dwconv_kernel<<<(QKV_CH * NPIX) / 256, 256>>>(qkvb, w_dw, b_dw,
                                                  q32, kh, kl, vh);

    // 4. tensor-core flash attention -> att [192,4096]
    {
        dim3 grid(NPIX / ATT_Q, HEADS);
        attn_mma_kernel<<<grid, 256, SMEM_BYTES>>>(q32, kh, kl, vh, temper, att);
    }

    // 5. out = w_proj @ att + x
    {
        dim3 grid(NPIX / 64, C_DIM / 64);
        gemm_kernel<<<grid, 256>>>(w_proj, att, x, out, C_DIM, C_DIM, NPIX);
    }
}

// round 10
// speedup vs baseline: 1.0446x; 1.0446x over previous
#include <cuda_runtime.h>
#include <cuda_fp16.h>
#include <cuda_bf16.h>
#include <cstdint>

// Problem constants
#define C_DIM   192
#define HEADS   8
#define HD      24          // head dim = 192/8
#define HH      64
#define WW      64
#define NPIX    4096        // 64*64
#define QKV_CH  576         // 3*C

// ---------------- scratch (static device globals; no allocs) ----------------
__device__ float g_xln[C_DIM * NPIX];                 // 3 MB
__device__ float g_qkv[QKV_CH * NPIX];                // 9 MB
__device__ float g_q32[C_DIM * NPIX];                 // 3 MB (dwconv Q out, fp32)
__device__ float g_att[C_DIM * NPIX];                 // 3 MB
// prepacked K (hi/lo fp16, [head][key][32] with cols 24..31 zero) and V fp16
__device__ unsigned short g_kh16[HEADS * NPIX * 32];  // 2 MB
__device__ unsigned short g_kl16[HEADS * NPIX * 32];  // 2 MB
__device__ unsigned short g_vh16[C_DIM * NPIX];       // 1.5 MB

// ---------------- small helpers ----------------
__device__ __forceinline__ float ex2f_fast(float x) {
    float r;
    asm("ex2.approx.f32 %0, %1;" : "=f"(r) : "f"(x));
    return r;
}

// packed fp16x2 exp2
__device__ __forceinline__ uint32_t h2ex2(uint32_t x) {
    uint32_t r;
    asm("ex2.approx.f16x2 %0, %1;" : "=r"(r) : "r"(x));
    return r;
}

// ---------------- Kernel 1: per-pixel LayerNorm over channels ----------------
__global__ void ln_kernel(const float* __restrict__ x,
                          const float* __restrict__ gamma,
                          const float* __restrict__ beta,
                          float* __restrict__ xln) {
    int p = blockIdx.x * blockDim.x + threadIdx.x;
    if (p >= NPIX) return;
    float s = 0.f, s2 = 0.f;
    #pragma unroll 8
    for (int c = 0; c < C_DIM; c++) {
        float v = x[c * NPIX + p];
        s += v;
        s2 = fmaf(v, v, s2);
    }
    const float invC = 1.0f / (float)C_DIM;
    float mean = s * invC;
    float var = s2 * invC - mean * mean;
    float inv = rsqrtf(var + 1e-5f);
    #pragma unroll 8
    for (int c = 0; c < C_DIM; c++) {
        float v = (x[c * NPIX + p] - mean) * inv;
        xln[c * NPIX + p] = fmaf(v, gamma[c], beta[c]);
    }
}

// ---------------- Kernel 2: GEMM  Y[O,N] = W[O,C] @ X[C,N] (+ optional residual) ----
__global__ __launch_bounds__(256) void gemm_kernel(
        const float* __restrict__ W, const float* __restrict__ X,
        const float* __restrict__ resid, float* __restrict__ Y,
        int O, int C, int N) {
    __shared__ __align__(16) float As[16][68];   // [k][o], padded
    __shared__ __align__(16) float Bs[16][64];   // [k][n]
    int tid = threadIdx.x;
    int tx = tid & 15;       // N dir
    int ty = tid >> 4;       // O dir
    int o0 = blockIdx.y * 64;
    int n0 = blockIdx.x * 64;

    float acc[4][4];
    #pragma unroll
    for (int i = 0; i < 4; i++)
        #pragma unroll
        for (int j = 0; j < 4; j++) acc[i][j] = 0.f;

    for (int k0 = 0; k0 < C; k0 += 16) {
        {
            int row = tid >> 2;
            int col = (tid & 3) * 4;
            float4 a = *(const float4*)&W[(o0 + row) * C + k0 + col];
            As[col + 0][row] = a.x;
            As[col + 1][row] = a.y;
            As[col + 2][row] = a.z;
            As[col + 3][row] = a.w;
        }
        {
            int row = tid >> 4;
            int col = (tid & 15) * 4;
            *(float4*)&Bs[row][col] = *(const float4*)&X[(k0 + row) * N + n0 + col];
        }
        __syncthreads();
        #pragma unroll
        for (int k = 0; k < 16; k++) {
            float4 a4 = *(const float4*)&As[k][ty * 4];
            float4 b4 = *(const float4*)&Bs[k][tx * 4];
            float a[4] = {a4.x, a4.y, a4.z, a4.w};
            float b[4] = {b4.x, b4.y, b4.z, b4.w};
            #pragma unroll
            for (int i = 0; i < 4; i++)
                #pragma unroll
                for (int j = 0; j < 4; j++)
                    acc[i][j] = fmaf(a[i], b[j], acc[i][j]);
        }
        __syncthreads();
    }

    #pragma unroll
    for (int i = 0; i < 4; i++) {
        int o = o0 + ty * 4 + i;
        int n = n0 + tx * 4;
        float4 r = make_float4(acc[i][0], acc[i][1], acc[i][2], acc[i][3]);
        if (resid) {
            float4 rv = *(const float4*)&resid[o * N + n];
            r.x += rv.x; r.y += rv.y; r.z += rv.z; r.w += rv.w;
        }
        *(float4*)&Y[o * N + n] = r;
    }
}

// ---------------- Kernel 3: depthwise 3x3 conv + bias, fused K/V prepack ----
__global__ void dwconv_kernel(const float* __restrict__ in,
                              const float* __restrict__ w,
                              const float* __restrict__ b,
                              float* __restrict__ qout,
                              unsigned short* __restrict__ kh,
                              unsigned short* __restrict__ kl,
                              unsigned short* __restrict__ vh) {
    int idx = blockIdx.x * blockDim.x + threadIdx.x;
    if (idx >= QKV_CH * NPIX) return;
    int p = idx & (NPIX - 1);
    int xx = idx & (WW - 1);
    int yy = (idx >> 6) & (HH - 1);
    int ch = idx >> 12;
    const float* wp = &w[ch * 9];
    const float* base = &in[ch * NPIX];
    float acc = b[ch];
    #pragma unroll
    for (int dy = -1; dy <= 1; dy++) {
        int y2 = yy + dy;
        if (y2 < 0 || y2 >= HH) continue;
        #pragma unroll
        for (int dx = -1; dx <= 1; dx++) {
            int x2 = xx + dx;
            if (x2 < 0 || x2 >= WW) continue;
            acc = fmaf(base[y2 * WW + x2], wp[(dy + 1) * 3 + (dx + 1)], acc);
        }
    }
    if (ch < C_DIM) {
        qout[idx] = acc;
    } else if (ch < 2 * C_DIM) {
        int cc = ch - C_DIM;
        int hh2 = cc / HD;
        int dd = cc % HD;
        __half hi = __float2half_rn(acc);
        float lo = acc - __half2float(hi);
        size_t o = ((size_t)(hh2 * NPIX + p)) * 32 + dd;
        kh[o] = __half_as_ushort(hi);
        kl[o] = __half_as_ushort(__float2half_rn(lo));
    } else {
        vh[(size_t)(ch - 2 * C_DIM) * NPIX + p] =
            __half_as_ushort(__float2half_rn(acc));
    }
}

// ---------------- Kernel 4: tensor-core flash attention ----------------
// 256 threads = 8 warps, 128 queries (16/warp), full 4096 keys in 64-key
// chunks. K/V prepacked fp16, cp.async 3-stage pipeline, 1 barrier/chunk.
// QK^T compensated hi/lo fp16. P via ex2.approx.f16x2. Row-sum l computed by
// the tensor core itself via an all-ones row appended to V (row 24).
#define ATT_Q  128
#define ATT_K  64
#define NCHUNK (NPIX / ATT_K)

// smem layout in halves (dynamic). Q/K rows padded to 40, V rows 72.
// V buffers are 32 rows: rows 0..23 = data (cp.async), row 24 = ones,
// rows 25..31 = zeros (set once).
#define OQH 0                         // Qh [128][40]
#define OQL 5120                      // Ql [128][40]
#define OKB 10240                     // K bufs: 3 x (hi 64*40 + lo 64*40)
#define OVB 25600                     // V bufs: 3 x 32*72
#define SM_HALVES (OVB + 3 * 2304)    // 32512
#define SMEM_BYTES (SM_HALVES * 2)    // 65024

__device__ __forceinline__ void mma16816(float c[4], const uint32_t a[4],
                                         uint32_t b0, uint32_t b1) {
    asm volatile(
        "mma.sync.aligned.m16n8k16.row.col.f32.f16.f16.f32 "
        "{%0,%1,%2,%3}, {%4,%5,%6,%7}, {%8,%9}, {%0,%1,%2,%3};"
        : "+f"(c[0]), "+f"(c[1]), "+f"(c[2]), "+f"(c[3])
        : "r"(a[0]), "r"(a[1]), "r"(a[2]), "r"(a[3]), "r"(b0), "r"(b1));
}

__device__ __forceinline__ void ldsm_x4(uint32_t& r0, uint32_t& r1,
                                        uint32_t& r2, uint32_t& r3, uint32_t addr) {
    asm volatile("ldmatrix.sync.aligned.m8n8.x4.shared.b16 {%0,%1,%2,%3}, [%4];"
                 : "=r"(r0), "=r"(r1), "=r"(r2), "=r"(r3) : "r"(addr));
}

__device__ __forceinline__ void cp16(uint32_t dst, const void* src) {
    asm volatile("cp.async.cg.shared.global [%0], [%1], 16;"
                 :: "r"(dst), "l"(src));
}

__device__ __forceinline__ uint32_t packh2(float x, float y) {
    __half2 h = __floats2half2_rn(x, y);   // low <- x, high <- y
    return *(uint32_t*)&h;
}

__global__ __launch_bounds__(256, 2) void attn_mma_kernel(
        const float* __restrict__ q32,
        const unsigned short* __restrict__ kh,
        const unsigned short* __restrict__ kl,
        const unsigned short* __restrict__ vh,
        const float* __restrict__ temp,
        float* __restrict__ att) {
    extern __shared__ __align__(16) __half sm[];
    const int tid = threadIdx.x;
    const int lane = tid & 31;
    const int warp = tid >> 5;
    const int g = lane >> 2;      // row group 0..7
    const int t = lane & 3;       // thread-in-group

    const int h = blockIdx.y;
    const int q0 = blockIdx.x * ATT_Q;
    const float scale = temp[h] * 1.4426950408889634f;  // temperature * log2(e)

    const float* qg = q32 + (h * HD) * NPIX;
    const unsigned short* khg = kh + (size_t)h * NPIX * 32;
    const unsigned short* klg = kl + (size_t)h * NPIX * 32;
    const unsigned short* vg  = vh + (size_t)(h * HD) * NPIX;

    const uint32_t smb = (uint32_t)__cvta_generic_to_shared(sm);

    // ---- init: zero Q region, zero K pad cols, set V rows 24..31 ----
    {
        uint32_t* smw = (uint32_t*)sm;
        for (int i = tid; i < 5120; i += 256) smw[i] = 0;          // Q hi/lo
        for (int i = tid; i < 1536; i += 256) {                    // K pads
            int wds = i & 3;
            int r2 = i >> 2;
            int buf = r2 >> 7;
            int rem = r2 & 127;
            int part = rem >> 6;
            int row = rem & 63;
            int halfoff = OKB + buf * 5120 + part * 2560 + row * 40 + 24;
            smw[(halfoff >> 1) + wds] = 0;
        }
        // V rows 24..31 of each buffer: row 24 = 1.0h, rows 25..31 = 0
        for (int i = tid; i < 3 * 8 * 72; i += 256) {
            int buf = i / 576;
            int rem = i - buf * 576;
            int row = rem / 72;            // 0..7 (maps to V row 24+row)
            int col = rem - row * 72;
            sm[OVB + buf * 2304 + (24 + row) * 72 + col] =
                (row == 0) ? __float2half_rn(1.0f) : __ushort_as_half(0);
        }
    }
    __syncthreads();

    // ---- issue cp.async for chunks 0 and 1 ----
    auto issue_chunk = [&](int b, int m0) {
        uint32_t kdstH = smb + (OKB + b * 5120) * 2;
        uint32_t kdstL = kdstH + 2560 * 2;
        uint32_t vdst  = smb + (OVB + b * 2304) * 2;
        #pragma unroll
        for (int i = tid; i < 576; i += 256) {
            if (i < 384) {
                int r = i;
                int part = r >= 192;
                r -= part * 192;
                int key = r / 3;
                int c = r - key * 3;
                const unsigned short* src =
                    (part ? klg : khg) + (size_t)(m0 + key) * 32 + c * 8;
                uint32_t dst = (part ? kdstL : kdstH) + (key * 40 + c * 8) * 2;
                cp16(dst, src);
            } else {
                int r = i - 384;
                int d = r >> 3;
                int c2 = r & 7;
                const unsigned short* src = vg + (size_t)d * NPIX + m0 + c2 * 8;
                uint32_t dst = vdst + (d * 72 + c2 * 8) * 2;
                cp16(dst, src);
            }
        }
        asm volatile("cp.async.commit_group;" ::: "memory");
    };
    issue_chunk(0, 0);
    issue_chunk(1, ATT_K);

    // ---- stage Q (scaled, hi/lo split) ----
    #pragma unroll
    for (int i = 0; i < 6; i++) {
        int e = tid + i * 256;            // 128 q * 12 d-pairs = 1536
        int dp = e >> 7;
        int qq = e & 127;
        float v0 = qg[(2 * dp) * NPIX + q0 + qq] * scale;
        float v1 = qg[(2 * dp + 1) * NPIX + q0 + qq] * scale;
        __half h0 = __float2half_rn(v0);
        __half h1 = __float2half_rn(v1);
        __half l0 = __float2half_rn(v0 - __half2float(h0));
        __half l1 = __float2half_rn(v1 - __half2float(h1));
        *(__half2*)&sm[OQH + qq * 40 + 2 * dp] = __halves2half2(h0, h1);
        *(__half2*)&sm[OQL + qq * 40 + 2 * dp] = __halves2half2(l0, l1);
    }
    __syncthreads();

    // ---- load Q A-fragments (2 k-steps over d 0..31; 24..31 zero pad) ----
    uint32_t aqh[2][4], aql[2][4];
    const int qr = warp * 16 + g;
    #pragma unroll
    for (int ks = 0; ks < 2; ks++) {
        int db = ks * 16 + t * 2;
        aqh[ks][0] = *(const uint32_t*)&sm[OQH + qr * 40 + db];
        aqh[ks][1] = *(const uint32_t*)&sm[OQH + (qr + 8) * 40 + db];
        aqh[ks][2] = *(const uint32_t*)&sm[OQH + qr * 40 + db + 8];
        aqh[ks][3] = *(const uint32_t*)&sm[OQH + (qr + 8) * 40 + db + 8];
        aql[ks][0] = *(const uint32_t*)&sm[OQL + qr * 40 + db];
        aql[ks][1] = *(const uint32_t*)&sm[OQL + (qr + 8) * 40 + db];
        aql[ks][2] = *(const uint32_t*)&sm[OQL + qr * 40 + db + 8];
        aql[ks][3] = *(const uint32_t*)&sm[OQL + (qr + 8) * 40 + db + 8];
    }

    // per-lane ldmatrix offsets
    const int l7 = lane & 7;
    const int lc = (lane >> 3) * 8;
    const uint32_t loff_k = (l7 * 40 + lc) * 2;
    const uint32_t loff_v = (l7 * 72 + lc) * 2;

    // out[0..2] = PV tiles (d 0..23); out[3] = ones-row tile (col 24 = row sum)
    float out[4][4];
    #pragma unroll
    for (int i = 0; i < 4; i++)
        #pragma unroll
        for (int j = 0; j < 4; j++) out[i][j] = 0.f;
    float m_a = -1e30f, m_b = -1e30f;   // row maxes (log2 units)

    for (int ch = 0; ch < NCHUNK; ch++) {
        if (ch < NCHUNK - 1)
            asm volatile("cp.async.wait_group 1;" ::: "memory");
        else
            asm volatile("cp.async.wait_group 0;" ::: "memory");
        __syncthreads();
        if (ch + 2 < NCHUNK) issue_chunk((ch + 2) % 3, (ch + 2) * ATT_K);

        const int b = ch % 3;
        const uint32_t kaddr_h = smb + (OKB + b * 5120) * 2 + loff_k;
        const uint32_t kaddr_l = kaddr_h + 2560 * 2;
        const uint32_t vaddr   = smb + (OVB + b * 2304) * 2 + loff_v;

        // ---- S = Q K^T (compensated), 8 n-tiles of 8 keys ----
        float s[8][4];
        #pragma unroll
        for (int nt = 0; nt < 8; nt++) {
            uint32_t h0, h1, h2, h3, L0, L1, L2, L3;
            ldsm_x4(h0, h1, h2, h3, kaddr_h + nt * 640);
            ldsm_x4(L0, L1, L2, L3, kaddr_l + nt * 640);
            s[nt][0] = s[nt][1] = s[nt][2] = s[nt][3] = 0.f;
            mma16816(s[nt], aqh[0], h0, h1);
            mma16816(s[nt], aqh[1], h2, h3);
            mma16816(s[nt], aql[0], h0, h1);
            mma16816(s[nt], aql[1], h2, h3);
            mma16816(s[nt], aqh[0], L0, L1);
            mma16816(s[nt], aqh[1], L2, L3);
        }

        // ---- online softmax (log2 domain) ----
        float ra = -1e30f, rb = -1e30f;
        #pragma unroll
        for (int nt = 0; nt < 8; nt++) {
            ra = fmaxf(ra, fmaxf(s[nt][0], s[nt][1]));
            rb = fmaxf(rb, fmaxf(s[nt][2], s[nt][3]));
        }
        ra = fmaxf(ra, __shfl_xor_sync(0xffffffffu, ra, 1));
        ra = fmaxf(ra, __shfl_xor_sync(0xffffffffu, ra, 2));
        rb = fmaxf(rb, __shfl_xor_sync(0xffffffffu, rb, 1));
        rb = fmaxf(rb, __shfl_xor_sync(0xffffffffu, rb, 2));
        float nma = fmaxf(m_a, ra);
        float nmb = fmaxf(m_b, rb);
        float ala = ex2f_fast(m_a - nma);
        float alb = ex2f_fast(m_b - nmb);
        m_a = nma; m_b = nmb;
        #pragma unroll
        for (int dnt = 0; dnt < 4; dnt++) {
            out[dnt][0] *= ala; out[dnt][1] *= ala;
            out[dnt][2] *= alb; out[dnt][3] *= alb;
        }

        // ---- P = exp2(S - m) directly in packed fp16 (A-layout fragments) ----
        uint32_t pa[4][4];
        #pragma unroll
        for (int kv = 0; kv < 4; kv++) {
            pa[kv][0] = h2ex2(packh2(s[2 * kv][0] - m_a,     s[2 * kv][1] - m_a));
            pa[kv][1] = h2ex2(packh2(s[2 * kv][2] - m_b,     s[2 * kv][3] - m_b));
            pa[kv][2] = h2ex2(packh2(s[2 * kv + 1][0] - m_a, s[2 * kv + 1][1] - m_a));
            pa[kv][3] = h2ex2(packh2(s[2 * kv + 1][2] - m_b, s[2 * kv + 1][3] - m_b));
        }

        // ---- out += P V  (4th tile = ones row -> row sums) ----
        #pragma unroll
        for (int dnt = 0; dnt < 4; dnt++) {
            uint32_t v0, v1, v2, v3, v4, v5, v6, v7;
            ldsm_x4(v0, v1, v2, v3, vaddr + dnt * 1152);        // keys 0..31
            ldsm_x4(v4, v5, v6, v7, vaddr + dnt * 1152 + 64);   // keys 32..63
            mma16816(out[dnt], pa[0], v0, v1);
            mma16816(out[dnt], pa[1], v2, v3);
            mma16816(out[dnt], pa[2], v4, v5);
            mma16816(out[dnt], pa[3], v6, v7);
        }
    }

    // ---- epilogue: l lives in out[3][0]/[2] of the t=0 lane of each quad ----
    float l_a = __shfl_sync(0xffffffffu, out[3][0], lane & ~3);
    float l_b = __shfl_sync(0xffffffffu, out[3][2], lane & ~3);
    float inva = 1.0f / l_a;
    float invb = 1.0f / l_b;
    int qa = q0 + warp * 16 + g;
    int qb = qa + 8;
    #pragma unroll
    for (int dnt = 0; dnt < 3; dnt++) {
        int c0 = h * HD + dnt * 8 + t * 2;
        att[c0 * NPIX + qa]       = out[dnt][0] * inva;
        att[(c0 + 1) * NPIX + qa] = out[dnt][1] * inva;
        att[c0 * NPIX + qb]       = out[dnt][2] * invb;
        att[(c0 + 1) * NPIX + qb] = out[dnt][3] * invb;
    }
}

// ---------------- launch ----------------
extern "C" void kernel_launch(void* const* d_in, const int* in_sizes, int n_in,
                              void* d_out, int out_size) {
    const float* x      = (const float*)d_in[0];   // [192,4096]
    const float* gamma  = (const float*)d_in[1];   // [192]
    const float* beta   = (const float*)d_in[2];   // [192]
    const float* w_qkv  = (const float*)d_in[3];   // [576,192]
    const float* w_dw   = (const float*)d_in[4];   // [576,9]
    const float* b_dw   = (const float*)d_in[5];   // [576]
    const float* w_proj = (const float*)d_in[6];   // [192,192]
    const float* temper = (const float*)d_in[7];   // [8]
    float* out = (float*)d_out;

    float *xln, *qkvb, *q32, *att;
    unsigned short *kh, *kl, *vh;
    cudaGetSymbolAddress((void**)&xln,  g_xln);
    cudaGetSymbolAddress((void**)&qkvb, g_qkv);
    cudaGetSymbolAddress((void**)&q32,  g_q32);
    cudaGetSymbolAddress((void**)&att,  g_att);
    cudaGetSymbolAddress((void**)&kh,   g_kh16);
    cudaGetSymbolAddress((void**)&kl,   g_kl16);
    cudaGetSymbolAddress((void**)&vh,   g_vh16);

    cudaFuncSetAttribute(attn_mma_kernel,
                         cudaFuncAttributeMaxDynamicSharedMemorySize, SMEM_BYTES);

    // 1. LayerNorm
    ln_kernel<<<NPIX / 256, 256>>>(x, gamma, beta, xln);

    // 2. qkv = w_qkv @ xln   [576,4096]
    {
        dim3 grid(NPIX / 64, QKV_CH / 64);
        gemm_kernel<<<grid, 256>>>(w_qkv, xln, nullptr, qkvb, QKV_CH, C_DIM, NPIX);
    }

    // 3. depthwise 3x3 + bias, fused K/V fp16 prepack
    dwconv_kernel<<<(QKV_CH * NPIX) / 256, 256>>>(qkvb, w_dw, b_dw,
                                                  q32, kh, kl, vh);

    // 4. tensor-core flash attention -> att [192,4096]
    {
        dim3 grid(NPIX / ATT_Q, HEADS);
        attn_mma_kernel<<<grid, 256, SMEM_BYTES>>>(q32, kh, kl, vh, temper, att);
    }

    // 5. out = w_proj @ att + x
    {
        dim3 grid(NPIX / 64, C_DIM / 64);
        gemm_kernel<<<grid, 256>>>(w_proj, att, x, out, C_DIM, C_DIM, NPIX);
    }
}